// round 8
// baseline (speedup 1.0000x reference)
#include <cuda_runtime.h>
#include <math.h>

// Problem constants
#define NB   2
#define NK   4096
#define NP   16384
#define NKP  (NB*NK)          // 8192 keypoint rows
#define CBEV 256
#define HH   496
#define WW   432
#define HW   (HH*WW)
#define R2   0.64f

// Grid for ball query (cell size = radius = 0.8)
#define GX 87
#define GY 100
#define GZ 5
#define NCELL (GX*GY*GZ)      // 43500
#define CAP 32

#define BEV_BLKS (NKP/4)      // 2048 bev blocks, 4 rows each
#define SA_BLKS  (NKP/8)      // 1024 sa blocks, 8 keypoints each

// GEMM: 16 rows per tile, K split in 4 quarters of 80 -> 2048 blocks x 128 threads
#define ROWS 16
#define KQ 80
#define GTILES (NKP/ROWS)     // 512 row tiles
#define NPART (GTILES*2)      // 1024 BN partial sets

// ---- scratch (static device globals; no allocation) ----
__device__ int   g_cellCnt[NB*NCELL];
__device__ int   g_cellPts[NB*NCELL*CAP];
__device__ float g_sa[NKP*64];
__device__ float g_pbev[NKP*CBEV];
__device__ float g_zp0[NKP*128];   // z partial, k in [0,80)
__device__ float g_zp1[NKP*128];   // z partial, k in [80,160)
__device__ float g_zp2[NKP*128];   // z partial, k in [160,240)
__device__ float g_zp3[NKP*128];   // z partial, k in [240,320)
__device__ float g_psum[NPART*128];
__device__ float g_psq [NPART*128];
__device__ float g_scale[128];
__device__ float g_shift[128];

__device__ __forceinline__ int cellOf(float x, float lo) {
    return (int)floorf((x - lo) * 1.25f);
}

__global__ void k_init() {
    int i = blockIdx.x*blockDim.x + threadIdx.x;
    if (i < NB*NCELL) g_cellCnt[i] = 0;
}

__global__ void k_bin(const float* __restrict__ pts) {
    int i = blockIdx.x*blockDim.x + threadIdx.x;
    if (i >= NB*NP) return;
    int b = i / NP, p = i % NP;
    float x = pts[i*3+0], y = pts[i*3+1], z = pts[i*3+2];
    int cx = min(max(cellOf(x,   0.0f), 0), GX-1);
    int cy = min(max(cellOf(y, -39.68f),0), GY-1);
    int cz = min(max(cellOf(z,  -3.0f), 0), GZ-1);
    int cell = b*NCELL + (cx*GY + cy)*GZ + cz;
    int slot = atomicAdd(&g_cellCnt[cell], 1);
    if (slot < CAP) g_cellPts[cell*CAP + slot] = p;   // set semantics; order-invariant downstream
}

// Fused: round-robin 2 bev blocks : 1 sa block so latency-bound sa warps stay
// co-resident with DRAM-bound bev warps for the whole kernel (no pure-sa tail).
__global__ void __launch_bounds__(256) k_sabev(
    const float* __restrict__ kps, const float* __restrict__ pts,
    const float* __restrict__ pf,  const float* __restrict__ bev,
    const float* __restrict__ W1, const float* __restrict__ b1,
    const float* __restrict__ W2, const float* __restrict__ b2)
{
    int t = threadIdx.x;
    int m = blockIdx.x % 3;           // 0,1 -> bev ; 2 -> sa
    int g = blockIdx.x / 3;

    if (m < 2) {
        // ---- BEV gather: 4 rows per block; thread: 2 rows x 2 channels = 16 LDGs ----
        int bi   = 2*g + m;           // 0..2047
        int c    = t & 127;
        int row0 = bi*4 + (t >> 7)*2;
        #pragma unroll
        for (int rr = 0; rr < 2; rr++) {
            int row = row0 + rr;
            int b = row >> 12;
            // match reference literally: (kx - 0)/0.16/1.0 ; (ky + 39.68)/0.16/1.0
            float x = kps[row*3+0] / 0.16f;
            float y = (kps[row*3+1] + 39.68f) / 0.16f;
            float fx = floorf(x), fy = floorf(y);
            int x0 = min(max((int)fx,     0), WW-1);
            int x1 = min(max((int)fx + 1, 0), WW-1);
            int y0 = min(max((int)fy,     0), HH-1);
            int y1 = min(max((int)fy + 1, 0), HH-1);
            float wa = ((float)x1 - x)*((float)y1 - y);
            float wb = ((float)x1 - x)*(y - (float)y0);
            float wc = (x - (float)x0)*((float)y1 - y);
            float wd = (x - (float)x0)*(y - (float)y0);
            const float* p0 = bev + ((size_t)b*CBEV + c)*(size_t)HW;
            const float* p1 = p0 + (size_t)128*HW;
            int oa = y0*WW + x0, ob = y1*WW + x0, oc = y0*WW + x1, od = y1*WW + x1;
            float A0 = __ldg(p0+oa), B0 = __ldg(p0+ob), C0 = __ldg(p0+oc), D0 = __ldg(p0+od);
            float A1 = __ldg(p1+oa), B1 = __ldg(p1+ob), C1 = __ldg(p1+oc), D1 = __ldg(p1+od);
            g_pbev[(size_t)row*CBEV + c]       = A0*wa + B0*wb + C0*wc + D0*wd;
            g_pbev[(size_t)row*CBEV + c + 128] = A1*wa + B1*wb + C1*wc + D1*wd;
        }
        return;
    }

    // ---- SA: one warp per keypoint, 8 warps per block ----
    __shared__ float W1s[128], b1s[32], W2s[2048], b2s[64];
    __shared__ int   cidx[8][128];
    __shared__ float cd2 [8][128];
    if (t < 128) W1s[t] = W1[t];
    for (int i = t; i < 2048; i += 256) W2s[i] = W2[i];
    if (t < 32) b1s[t] = b1[t];
    if (t < 64) b2s[t] = b2[t];
    __syncthreads();

    int warp = t >> 5, lane = t & 31;
    int kpi = g*8 + warp;             // 0..8191
    int b = kpi >> 12;
    float kx = kps[kpi*3+0], ky = kps[kpi*3+1], kz = kps[kpi*3+2];
    int cx = min(max(cellOf(kx,   0.0f), 0), GX-1);
    int cy = min(max(cellOf(ky, -39.68f),0), GY-1);
    int cz = min(max(cellOf(kz,  -3.0f), 0), GZ-1);

    const float* ptsb = pts + (size_t)b*NP*3;

    int n_l = 0;
    const int* cp_l = g_cellPts;
    if (lane < 27) {
        int ccx = cx + lane/9 - 1;
        int ccy = cy + (lane/3)%3 - 1;
        int ccz = cz + lane%3 - 1;
        if (ccx >= 0 && ccx < GX && ccy >= 0 && ccy < GY && ccz >= 0 && ccz < GZ) {
            int cell = b*NCELL + (ccx*GY + ccy)*GZ + ccz;
            n_l = min(g_cellCnt[cell], CAP);
            cp_l = &g_cellPts[cell*CAP];
        }
    }
    int maxn = n_l;
    #pragma unroll
    for (int o = 16; o; o >>= 1) maxn = max(maxn, __shfl_xor_sync(0xffffffffu, maxn, o));

    int cnt = 0;
    for (int s = 0; s < maxn; s++) {
        bool act = s < n_l;
        int pi = act ? cp_l[s] : 0;
        float d2 = 1e30f;
        if (act) {
            float ddx = ptsb[pi*3+0]-kx;
            float ddy = ptsb[pi*3+1]-ky;
            float ddz = ptsb[pi*3+2]-kz;
            d2 = ddx*ddx + ddy*ddy + ddz*ddz;
        }
        bool val = act && (d2 < R2);
        unsigned mm = __ballot_sync(0xffffffffu, val);
        int pos = cnt + __popc(mm & ((1u<<lane)-1u));
        if (val && pos < 128) { cidx[warp][pos] = pi; cd2[warp][pos] = d2; }
        cnt += __popc(mm);
    }
    if (cnt > 128) cnt = 128;
    __syncwarp();
    if (cnt > 32) {   // ultra-rare: keep 32 smallest d2 (same set as top_k; order irrelevant for maxpool)
        if (lane == 0) {
            for (int i = 32; i < cnt; i++) {
                float d = cd2[warp][i];
                int mi = 0; float mv = cd2[warp][0];
                for (int j = 1; j < 32; j++) { float v = cd2[warp][j]; if (v > mv) { mv = v; mi = j; } }
                if (d < mv) { cd2[warp][mi] = d; cidx[warp][mi] = cidx[warp][i]; }
            }
        }
        __syncwarp();
        cnt = 32;
    }

    float w10 = W1s[lane], w11 = W1s[32+lane], w12 = W1s[64+lane], w13 = W1s[96+lane];
    float b1v = b1s[lane];
    float a0 = 0.f, a1 = 0.f;   // relu >= 0 so 0-init == reference no-valid case
    const float* pfb = pf + (size_t)b*NP;
    for (int nIt = 0; nIt < cnt; nIt++) {
        int pi = cidx[warp][nIt];
        float dx = ptsb[pi*3+0]-kx;
        float dy = ptsb[pi*3+1]-ky;
        float dz = ptsb[pi*3+2]-kz;
        float f  = pfb[pi];
        float hv = fmaxf(fmaf(dx,w10, fmaf(dy,w11, fmaf(dz,w12, fmaf(f,w13, b1v)))), 0.f);
        float t0 = b2s[lane], t1 = b2s[32+lane];
        #pragma unroll
        for (int j = 0; j < 32; j++) {
            float hj = __shfl_sync(0xffffffffu, hv, j);
            t0 = fmaf(hj, W2s[j*64+lane],    t0);
            t1 = fmaf(hj, W2s[j*64+32+lane], t1);
        }
        a0 = fmaxf(a0, fmaxf(t0, 0.f));
        a1 = fmaxf(a1, fmaxf(t1, 0.f));
    }
    g_sa[kpi*64 + lane]      = a0;
    g_sa[kpi*64 + 32 + lane] = a1;
}

// GEMM, K split in 4: block -> row tile (16 rows) x k-quarter (80 k-values).
// 128 threads: cp (0..63) owns adjacent columns {2cp, 2cp+1}; h (0..1) owns pairs h*4..h*4+3.
// Per kk-iter: 4 LDS.128 (features) + 2 LDG.64 (weights) + 4 packs + 16 FFMA2.
// fma.rn.f32x2 is bit-identical to 2x scalar fma.rn.
__global__ void __launch_bounds__(128) k_gemm(const float* __restrict__ Wf)
{
    __shared__ float fsp[8*160];   // pair p: element (kk,parity) at [p*160 + 2kk + parity]
    int t = threadIdx.x;
    int tile = blockIdx.x >> 2, q = blockIdx.x & 3;
    int r0 = tile * ROWS;
    int k0 = q * KQ;

    for (int i = t; i < ROWS*KQ; i += 128) {
        int r = i / KQ, kk = i - r*KQ;
        int k = k0 + kk;
        float v = (k < 64) ? g_sa[(size_t)(r0+r)*64 + k]
                           : g_pbev[(size_t)(r0+r)*CBEV + (k-64)];
        fsp[(r>>1)*160 + 2*kk + (r&1)] = v;
    }
    __syncthreads();

    int cp = t & 63, h = t >> 6;
    int c0 = 2*cp;
    unsigned long long acc[4][2];    // [pair j][col 0/1], lanes = {even row, odd row}
    #pragma unroll
    for (int j = 0; j < 4; j++) { acc[j][0] = 0ull; acc[j][1] = 0ull; }

    const float2* wp = (const float2*)Wf + (size_t)k0*64 + cp;   // [k][col-pair cp]
    const float* base = fsp + (h*4)*160;
    for (int kk = 0; kk < KQ; kk += 2) {
        float2 wA = __ldg(wp + (size_t)kk*64);       // k0+kk:   {w_c0, w_c1}
        float2 wB = __ldg(wp + (size_t)(kk+1)*64);   // k0+kk+1: {w_c0, w_c1}
        unsigned long long wA0, wA1, wB0, wB1;
        asm("mov.b64 %0,{%1,%1};" : "=l"(wA0) : "f"(wA.x));
        asm("mov.b64 %0,{%1,%1};" : "=l"(wA1) : "f"(wA.y));
        asm("mov.b64 %0,{%1,%1};" : "=l"(wB0) : "f"(wB.x));
        asm("mov.b64 %0,{%1,%1};" : "=l"(wB1) : "f"(wB.y));
        #pragma unroll
        for (int j = 0; j < 4; j++) {
            longlong2 qv = *(const longlong2*)(base + j*160 + 2*kk);   // LDS.128 broadcast
            asm("fma.rn.f32x2 %0,%1,%2,%0;" : "+l"(acc[j][0]) : "l"((unsigned long long)qv.x), "l"(wA0));
            asm("fma.rn.f32x2 %0,%1,%2,%0;" : "+l"(acc[j][1]) : "l"((unsigned long long)qv.x), "l"(wA1));
            asm("fma.rn.f32x2 %0,%1,%2,%0;" : "+l"(acc[j][0]) : "l"((unsigned long long)qv.y), "l"(wB0));
            asm("fma.rn.f32x2 %0,%1,%2,%0;" : "+l"(acc[j][1]) : "l"((unsigned long long)qv.y), "l"(wB1));
        }
    }

    float* zp = (q == 0) ? g_zp0 : (q == 1) ? g_zp1 : (q == 2) ? g_zp2 : g_zp3;
    #pragma unroll
    for (int j = 0; j < 4; j++) {
        float e0, o0, e1, o1;
        asm("mov.b64 {%0,%1},%2;" : "=f"(e0), "=f"(o0) : "l"(acc[j][0]));
        asm("mov.b64 {%0,%1},%2;" : "=f"(e1), "=f"(o1) : "l"(acc[j][1]));
        int p = h*4 + j;
        float2* re = (float2*)(zp + (size_t)(r0 + 2*p    )*128 + c0);
        float2* ro = (float2*)(zp + (size_t)(r0 + 2*p + 1)*128 + c0);
        *re = make_float2(e0, e1);   // STG.64: cols c0, c0+1 of even row
        *ro = make_float2(o0, o1);
    }
}

// BN partials from z = zp0+zp1+zp2+zp3: 512 blocks x 256 threads; (block, half) owns 8 rows.
__global__ void __launch_bounds__(256) k_part() {
    int h = threadIdx.x >> 7, c = threadIdx.x & 127;
    int row0 = blockIdx.x*16 + h*8;
    float s = 0.f, q = 0.f;
    #pragma unroll
    for (int r = 0; r < 8; r++) {
        size_t i = (size_t)(row0 + r)*128 + c;
        float z = (g_zp0[i] + g_zp1[i]) + (g_zp2[i] + g_zp3[i]);
        s += z; q += z*z;
    }
    g_psum[(blockIdx.x*2 + h)*128 + c] = s;
    g_psq [(blockIdx.x*2 + h)*128 + c] = q;
}

// One block per channel; 256 threads reduce 1024 partials. Deterministic.
__global__ void __launch_bounds__(256) k_stats(
    const float* __restrict__ gamma, const float* __restrict__ beta)
{
    __shared__ float sh_s[256], sh_q[256];
    int c = blockIdx.x, t = threadIdx.x;
    float s = 0.f, q = 0.f;
    #pragma unroll
    for (int i = t; i < NPART; i += 256) { s += g_psum[i*128+c]; q += g_psq[i*128+c]; }
    sh_s[t] = s; sh_q[t] = q;
    __syncthreads();
    #pragma unroll
    for (int o = 128; o; o >>= 1) {
        if (t < o) { sh_s[t] += sh_s[t+o]; sh_q[t] += sh_q[t+o]; }
        __syncthreads();
    }
    if (t == 0) {
        float inv = 1.0f / (float)NKP;
        float mu  = sh_s[0] * inv;
        float var = sh_q[0] * inv - mu*mu;
        float sc  = rsqrtf(var + 1e-5f) * gamma[c];
        g_scale[c] = sc;
        g_shift[c] = beta[c] - mu * sc;
    }
}

__global__ void k_norm(float* __restrict__ out) {
    int i = blockIdx.x*blockDim.x + threadIdx.x;
    int c = i & 127;
    float z = (g_zp0[i] + g_zp1[i]) + (g_zp2[i] + g_zp3[i]);
    out[i] = fmaxf(fmaf(z, g_scale[c], g_shift[c]), 0.f);
}

extern "C" void kernel_launch(void* const* d_in, const int* /*in_sizes*/, int /*n_in*/,
                              void* d_out, int /*out_size*/) {
    const float* kps = (const float*)d_in[0];
    const float* pts = (const float*)d_in[1];
    const float* pf  = (const float*)d_in[2];
    const float* bev = (const float*)d_in[3];
    const float* W1  = (const float*)d_in[4];
    const float* b1  = (const float*)d_in[5];
    const float* W2  = (const float*)d_in[6];
    const float* b2  = (const float*)d_in[7];
    const float* Wf  = (const float*)d_in[8];
    const float* gm  = (const float*)d_in[9];
    const float* bt  = (const float*)d_in[10];

    k_init <<<(NB*NCELL + 255)/256, 256>>>();
    k_bin  <<<(NB*NP    + 255)/256, 256>>>(pts);
    k_sabev<<<BEV_BLKS + SA_BLKS, 256>>>(kps, pts, pf, bev, W1, b1, W2, b2);
    k_gemm <<<GTILES*4, 128>>>(Wf);
    k_part <<<GTILES, 256>>>();
    k_stats<<<128, 256>>>(gm, bt);
    k_norm <<<(NKP*128)/256, 256>>>((float*)d_out);
}

// round 9
// speedup vs baseline: 1.1017x; 1.1017x over previous
#include <cuda_runtime.h>
#include <math.h>

// Problem constants
#define NB   2
#define NK   4096
#define NP   16384
#define NKP  (NB*NK)          // 8192 keypoint rows
#define CBEV 256
#define HH   496
#define WW   432
#define HW   (HH*WW)
#define R2   0.64f

// Grid for ball query (cell size = radius = 0.8)
#define GX 87
#define GY 100
#define GZ 5
#define NCELL (GX*GY*GZ)      // 43500
#define CAP 32

#define NTILES (NKP/16)       // 512 tiles of 16 rows
#define NPART (NTILES*2)      // 1024 BN partial sets
#define BEV_BLKS (NKP/4)      // 2048 bev blocks, 4 rows each
#define SA_BLKS  (NKP/8)      // 1024 sa blocks, 8 keypoints each

// ---- scratch (static device globals; no allocation) ----
__device__ int   g_cellCnt[NB*NCELL];
__device__ int   g_cellPts[NB*NCELL*CAP];
__device__ int   g_tilecnt[NTILES];
__device__ float g_sa[NKP*64];
__device__ float g_pbev[NKP*CBEV];
__device__ float g_Z[NKP*128];
__device__ float g_psum[NPART*128];
__device__ float g_psq [NPART*128];
__device__ float g_scale[128];
__device__ float g_shift[128];

__device__ __forceinline__ int cellOf(float x, float lo) {
    return (int)floorf((x - lo) * 1.25f);
}

__global__ void k_init() {
    int i = blockIdx.x*blockDim.x + threadIdx.x;
    if (i < NB*NCELL) g_cellCnt[i] = 0;
    if (i < NTILES)   g_tilecnt[i] = 0;
}

__global__ void k_bin(const float* __restrict__ pts) {
    int i = blockIdx.x*blockDim.x + threadIdx.x;
    if (i >= NB*NP) return;
    int b = i / NP, p = i % NP;
    float x = pts[i*3+0], y = pts[i*3+1], z = pts[i*3+2];
    int cx = min(max(cellOf(x,   0.0f), 0), GX-1);
    int cy = min(max(cellOf(y, -39.68f),0), GY-1);
    int cz = min(max(cellOf(z,  -3.0f), 0), GZ-1);
    int cell = b*NCELL + (cx*GY + cy)*GZ + cz;
    int slot = atomicAdd(&g_cellCnt[cell], 1);
    if (slot < CAP) g_cellPts[cell*CAP + slot] = p;   // set semantics; order-invariant downstream
}

// Full-K tile GEMM: 16 rows x 320 @ 320 x 128 -> g_Z. 256 threads.
// Row pairs packed as f32x2; fma.rn.f32x2 is bit-identical to 2x scalar fma.rn.
__device__ __forceinline__ void tile_gemm(int tile, const float* __restrict__ Wf, float* fsp) {
    int t = threadIdx.x;
    int r0 = tile * 16;
    for (int i = t; i < 16*320; i += 256) {
        int r = i / 320, k = i - r*320;
        float v = (k < 64) ? g_sa[(size_t)(r0+r)*64 + k]
                           : g_pbev[(size_t)(r0+r)*CBEV + (k-64)];
        fsp[(r>>1)*640 + 2*k + (r&1)] = v;
    }
    __syncthreads();

    int h = t >> 7, c = t & 127;
    unsigned long long acc[4];
    #pragma unroll
    for (int j = 0; j < 4; j++) acc[j] = 0ull;

    const float* wcol = Wf + c;
    const float* base = fsp + (h*4)*640;
    for (int k = 0; k < 320; k += 2) {
        float wa = wcol[(size_t)k*128];
        float wb = wcol[(size_t)(k+1)*128];
        unsigned long long w2a, w2b;
        asm("mov.b64 %0,{%1,%1};" : "=l"(w2a) : "f"(wa));
        asm("mov.b64 %0,{%1,%1};" : "=l"(w2b) : "f"(wb));
        #pragma unroll
        for (int j = 0; j < 4; j++) {
            longlong2 q = *(const longlong2*)(base + j*640 + 2*k);   // LDS.128 broadcast
            asm("fma.rn.f32x2 %0,%1,%2,%0;" : "+l"(acc[j]) : "l"((unsigned long long)q.x), "l"(w2a));
            asm("fma.rn.f32x2 %0,%1,%2,%0;" : "+l"(acc[j]) : "l"((unsigned long long)q.y), "l"(w2b));
        }
    }

    #pragma unroll
    for (int j = 0; j < 4; j++) {
        float zlo, zhi;
        asm("mov.b64 {%0,%1},%2;" : "=f"(zlo), "=f"(zhi) : "l"(acc[j]));
        int p = h*4 + j;
        g_Z[(size_t)(r0 + 2*p    )*128 + c] = zlo;
        g_Z[(size_t)(r0 + 2*p + 1)*128 + c] = zhi;
    }
}

// Fused producer kernel with embedded tile GEMM ("last arriver executes").
// Tile t (16 rows) producers: bev blocks 4t..4t+3 (4 rows each) + sa blocks 2t, 2t+1 (8 kps each).
// Each producer: work -> __threadfence -> atomicAdd(tilecnt). The 6th finisher runs tile_gemm,
// so GEMM issue work hides under other blocks' DRAM-bound gathers. Values & fp order are
// identical regardless of which block executes -> deterministic.
__global__ void __launch_bounds__(256, 6) k_sabev(
    const float* __restrict__ kps, const float* __restrict__ pts,
    const float* __restrict__ pf,  const float* __restrict__ bev,
    const float* __restrict__ W1, const float* __restrict__ b1,
    const float* __restrict__ W2, const float* __restrict__ b2,
    const float* __restrict__ Wf)
{
    __shared__ union SH {
        float fsp[8*640];   // 20 KB GEMM workspace
        struct {
            float W1s[128], b1s[32], W2s[2048], b2s[64];
            int   cidx[8][128];
            float cd2 [8][128];
        } mlp;
    } sh;
    __shared__ int sh_win;

    int t = threadIdx.x;
    int m = blockIdx.x % 3;           // 0,1 -> bev ; 2 -> sa
    int g = blockIdx.x / 3;
    int tile;

    if (m < 2) {
        // ---- BEV gather: 4 rows per block; thread: 2 rows x 2 channels = 16 LDGs ----
        int bi   = 2*g + m;           // 0..2047
        tile     = bi >> 2;
        int c    = t & 127;
        int row0 = bi*4 + (t >> 7)*2;
        #pragma unroll
        for (int rr = 0; rr < 2; rr++) {
            int row = row0 + rr;
            int b = row >> 12;
            // match reference literally: (kx - 0)/0.16/1.0 ; (ky + 39.68)/0.16/1.0
            float x = kps[row*3+0] / 0.16f;
            float y = (kps[row*3+1] + 39.68f) / 0.16f;
            float fx = floorf(x), fy = floorf(y);
            int x0 = min(max((int)fx,     0), WW-1);
            int x1 = min(max((int)fx + 1, 0), WW-1);
            int y0 = min(max((int)fy,     0), HH-1);
            int y1 = min(max((int)fy + 1, 0), HH-1);
            float wa = ((float)x1 - x)*((float)y1 - y);
            float wb = ((float)x1 - x)*(y - (float)y0);
            float wc = (x - (float)x0)*((float)y1 - y);
            float wd = (x - (float)x0)*(y - (float)y0);
            const float* p0 = bev + ((size_t)b*CBEV + c)*(size_t)HW;
            const float* p1 = p0 + (size_t)128*HW;
            int oa = y0*WW + x0, ob = y1*WW + x0, oc = y0*WW + x1, od = y1*WW + x1;
            float A0 = __ldg(p0+oa), B0 = __ldg(p0+ob), C0 = __ldg(p0+oc), D0 = __ldg(p0+od);
            float A1 = __ldg(p1+oa), B1 = __ldg(p1+ob), C1 = __ldg(p1+oc), D1 = __ldg(p1+od);
            g_pbev[(size_t)row*CBEV + c]       = A0*wa + B0*wb + C0*wc + D0*wd;
            g_pbev[(size_t)row*CBEV + c + 128] = A1*wa + B1*wb + C1*wc + D1*wd;
        }
    } else {
        // ---- SA: one warp per keypoint, 8 warps per block ----
        tile = g >> 1;
        if (t < 128) sh.mlp.W1s[t] = W1[t];
        for (int i = t; i < 2048; i += 256) sh.mlp.W2s[i] = W2[i];
        if (t < 32) sh.mlp.b1s[t] = b1[t];
        if (t < 64) sh.mlp.b2s[t] = b2[t];
        __syncthreads();

        int warp = t >> 5, lane = t & 31;
        int kpi = g*8 + warp;             // 0..8191
        int b = kpi >> 12;
        float kx = kps[kpi*3+0], ky = kps[kpi*3+1], kz = kps[kpi*3+2];
        int cx = min(max(cellOf(kx,   0.0f), 0), GX-1);
        int cy = min(max(cellOf(ky, -39.68f),0), GY-1);
        int cz = min(max(cellOf(kz,  -3.0f), 0), GZ-1);

        const float* ptsb = pts + (size_t)b*NP*3;

        int n_l = 0;
        const int* cp_l = g_cellPts;
        if (lane < 27) {
            int ccx = cx + lane/9 - 1;
            int ccy = cy + (lane/3)%3 - 1;
            int ccz = cz + lane%3 - 1;
            if (ccx >= 0 && ccx < GX && ccy >= 0 && ccy < GY && ccz >= 0 && ccz < GZ) {
                int cell = b*NCELL + (ccx*GY + ccy)*GZ + ccz;
                n_l = min(g_cellCnt[cell], CAP);
                cp_l = &g_cellPts[cell*CAP];
            }
        }
        int maxn = n_l;
        #pragma unroll
        for (int o = 16; o; o >>= 1) maxn = max(maxn, __shfl_xor_sync(0xffffffffu, maxn, o));

        int cnt = 0;
        for (int s = 0; s < maxn; s++) {
            bool act = s < n_l;
            int pi = act ? cp_l[s] : 0;
            float d2 = 1e30f;
            if (act) {
                float ddx = ptsb[pi*3+0]-kx;
                float ddy = ptsb[pi*3+1]-ky;
                float ddz = ptsb[pi*3+2]-kz;
                d2 = ddx*ddx + ddy*ddy + ddz*ddz;
            }
            bool val = act && (d2 < R2);
            unsigned mm = __ballot_sync(0xffffffffu, val);
            int pos = cnt + __popc(mm & ((1u<<lane)-1u));
            if (val && pos < 128) { sh.mlp.cidx[warp][pos] = pi; sh.mlp.cd2[warp][pos] = d2; }
            cnt += __popc(mm);
        }
        if (cnt > 128) cnt = 128;
        __syncwarp();
        if (cnt > 32) {   // ultra-rare: keep 32 smallest d2 (same set as top_k; order irrelevant for maxpool)
            if (lane == 0) {
                for (int i = 32; i < cnt; i++) {
                    float d = sh.mlp.cd2[warp][i];
                    int mi = 0; float mv = sh.mlp.cd2[warp][0];
                    for (int j = 1; j < 32; j++) { float v = sh.mlp.cd2[warp][j]; if (v > mv) { mv = v; mi = j; } }
                    if (d < mv) { sh.mlp.cd2[warp][mi] = d; sh.mlp.cidx[warp][mi] = sh.mlp.cidx[warp][i]; }
                }
            }
            __syncwarp();
            cnt = 32;
        }

        float w10 = sh.mlp.W1s[lane], w11 = sh.mlp.W1s[32+lane];
        float w12 = sh.mlp.W1s[64+lane], w13 = sh.mlp.W1s[96+lane];
        float b1v = sh.mlp.b1s[lane];
        float a0 = 0.f, a1 = 0.f;   // relu >= 0 so 0-init == reference no-valid case
        const float* pfb = pf + (size_t)b*NP;
        for (int nIt = 0; nIt < cnt; nIt++) {
            int pi = sh.mlp.cidx[warp][nIt];
            float dx = ptsb[pi*3+0]-kx;
            float dy = ptsb[pi*3+1]-ky;
            float dz = ptsb[pi*3+2]-kz;
            float f  = pfb[pi];
            float hv = fmaxf(fmaf(dx,w10, fmaf(dy,w11, fmaf(dz,w12, fmaf(f,w13, b1v)))), 0.f);
            float t0 = sh.mlp.b2s[lane], t1 = sh.mlp.b2s[32+lane];
            #pragma unroll
            for (int j = 0; j < 32; j++) {
                float hj = __shfl_sync(0xffffffffu, hv, j);
                t0 = fmaf(hj, sh.mlp.W2s[j*64+lane],    t0);
                t1 = fmaf(hj, sh.mlp.W2s[j*64+32+lane], t1);
            }
            a0 = fmaxf(a0, fmaxf(t0, 0.f));
            a1 = fmaxf(a1, fmaxf(t1, 0.f));
        }
        g_sa[kpi*64 + lane]      = a0;
        g_sa[kpi*64 + 32 + lane] = a1;
    }

    // ---- release: make this block's writes visible, then count in ----
    __threadfence();
    __syncthreads();          // all threads' fences done; union no longer in mlp use
    if (t == 0) {
        int old = atomicAdd(&g_tilecnt[tile], 1);
        sh_win = (old == 5);
    }
    __syncthreads();
    if (sh_win) {
        __threadfence();      // acquire: flush L1 before reading other blocks' g_sa/g_pbev
        tile_gemm(tile, Wf, sh.fsp);
    }
}

// BN partials: 512 blocks x 256 threads; (block, half) owns 8 rows of g_Z.
__global__ void __launch_bounds__(256) k_part() {
    int h = threadIdx.x >> 7, c = threadIdx.x & 127;
    int row0 = blockIdx.x*16 + h*8;
    float s = 0.f, q = 0.f;
    #pragma unroll
    for (int r = 0; r < 8; r++) {
        float z = g_Z[(size_t)(row0 + r)*128 + c];
        s += z; q += z*z;
    }
    g_psum[(blockIdx.x*2 + h)*128 + c] = s;
    g_psq [(blockIdx.x*2 + h)*128 + c] = q;
}

// One block per channel; 256 threads reduce 1024 partials. Deterministic.
__global__ void __launch_bounds__(256) k_stats(
    const float* __restrict__ gamma, const float* __restrict__ beta)
{
    __shared__ float sh_s[256], sh_q[256];
    int c = blockIdx.x, t = threadIdx.x;
    float s = 0.f, q = 0.f;
    #pragma unroll
    for (int i = t; i < NPART; i += 256) { s += g_psum[i*128+c]; q += g_psq[i*128+c]; }
    sh_s[t] = s; sh_q[t] = q;
    __syncthreads();
    #pragma unroll
    for (int o = 128; o; o >>= 1) {
        if (t < o) { sh_s[t] += sh_s[t+o]; sh_q[t] += sh_q[t+o]; }
        __syncthreads();
    }
    if (t == 0) {
        float inv = 1.0f / (float)NKP;
        float mu  = sh_s[0] * inv;
        float var = sh_q[0] * inv - mu*mu;
        float sc  = rsqrtf(var + 1e-5f) * gamma[c];
        g_scale[c] = sc;
        g_shift[c] = beta[c] - mu * sc;
    }
}

__global__ void k_norm(float* __restrict__ out) {
    int i = blockIdx.x*blockDim.x + threadIdx.x;
    int c = i & 127;
    out[i] = fmaxf(fmaf(g_Z[i], g_scale[c], g_shift[c]), 0.f);
}

extern "C" void kernel_launch(void* const* d_in, const int* /*in_sizes*/, int /*n_in*/,
                              void* d_out, int /*out_size*/) {
    const float* kps = (const float*)d_in[0];
    const float* pts = (const float*)d_in[1];
    const float* pf  = (const float*)d_in[2];
    const float* bev = (const float*)d_in[3];
    const float* W1  = (const float*)d_in[4];
    const float* b1  = (const float*)d_in[5];
    const float* W2  = (const float*)d_in[6];
    const float* b2  = (const float*)d_in[7];
    const float* Wf  = (const float*)d_in[8];
    const float* gm  = (const float*)d_in[9];
    const float* bt  = (const float*)d_in[10];

    k_init <<<(NB*NCELL + 255)/256, 256>>>();
    k_bin  <<<(NB*NP    + 255)/256, 256>>>(pts);
    k_sabev<<<BEV_BLKS + SA_BLKS, 256>>>(kps, pts, pf, bev, W1, b1, W2, b2, Wf);
    k_part <<<NTILES, 256>>>();
    k_stats<<<128, 256>>>(gm, bt);
    k_norm <<<(NKP*128)/256, 256>>>((float*)d_out);
}

// round 10
// speedup vs baseline: 1.1271x; 1.0231x over previous
#include <cuda_runtime.h>
#include <math.h>

// Problem constants
#define NB   2
#define NK   4096
#define NP   16384
#define NKP  (NB*NK)          // 8192 keypoint rows
#define CBEV 256
#define HH   496
#define WW   432
#define HW   (HH*WW)
#define R2   0.64f

// Grid for ball query (cell size = radius = 0.8)
#define GX 87
#define GY 100
#define GZ 5
#define NCELL (GX*GY*GZ)      // 43500
#define CAP 32

#define NTILES (NKP/16)       // 512 tiles of 16 rows
#define NPART (NTILES*2)      // 1024 BN partial sets
#define BEV_BLKS (NKP/4)      // 2048 bev blocks, 4 rows each
#define SA_BLKS  (NKP/8)      // 1024 sa blocks, 8 keypoints each

// ---- scratch (static device globals; no allocation) ----
__device__ int   g_cellCnt[NB*NCELL];
__device__ int   g_cellPts[NB*NCELL*CAP];
__device__ int   g_tilecnt[NTILES];
__device__ float g_sa[NKP*64];
__device__ float g_pbev[NKP*CBEV];
__device__ float g_Z[NKP*128];
__device__ float g_psum[NPART*128];
__device__ float g_psq [NPART*128];
__device__ float g_scale[128];
__device__ float g_shift[128];

__device__ __forceinline__ int cellOf(float x, float lo) {
    return (int)floorf((x - lo) * 1.25f);
}

__global__ void k_bin(const float* __restrict__ pts) {
    int i = blockIdx.x*blockDim.x + threadIdx.x;
    if (i >= NB*NP) return;
    int b = i / NP, p = i % NP;
    float x = pts[i*3+0], y = pts[i*3+1], z = pts[i*3+2];
    int cx = min(max(cellOf(x,   0.0f), 0), GX-1);
    int cy = min(max(cellOf(y, -39.68f),0), GY-1);
    int cz = min(max(cellOf(z,  -3.0f), 0), GZ-1);
    int cell = b*NCELL + (cx*GY + cy)*GZ + cz;
    int slot = atomicAdd(&g_cellCnt[cell], 1);
    if (slot < CAP) g_cellPts[cell*CAP + slot] = p;   // set semantics; order-invariant downstream
}

// Full-K tile GEMM + BN partials. Stage with 256 threads; compute with 128 threads:
// thread (h = t>>6 in 0..1, cp = t&63) owns 8 rows (pairs h*4..h*4+3) x 2 cols {2cp,2cp+1}.
// Per k-pair iter: 2 LDG.64 + 4 packs + 4 LDS.128 + 16 FFMA2  (0.81 instr/MAC, low L1/MAC).
// fma.rn.f32x2 is bit-identical to 2x scalar fma.rn.
__device__ __forceinline__ void tile_gemm(int tile, const float* __restrict__ Wf, float* fsp) {
    int t = threadIdx.x;
    int r0 = tile * 16;
    for (int i = t; i < 16*320; i += 256) {
        int r = i / 320, k = i - r*320;
        float v = (k < 64) ? g_sa[(size_t)(r0+r)*64 + k]
                           : g_pbev[(size_t)(r0+r)*CBEV + (k-64)];
        fsp[(r>>1)*640 + 2*k + (r&1)] = v;
    }
    __syncthreads();
    if (t >= 128) return;

    int h = t >> 6, cp = t & 63;
    int c0 = 2*cp;
    unsigned long long acc[4][2];
    #pragma unroll
    for (int j = 0; j < 4; j++) { acc[j][0] = 0ull; acc[j][1] = 0ull; }

    const float2* wp = (const float2*)Wf + cp;     // element (k, colpair cp) at k*64+cp
    const float* base = fsp + (h*4)*640;
    for (int k = 0; k < 320; k += 2) {
        float2 wA = __ldg(wp + (size_t)k*64);       // k:   {w_c0, w_c1}
        float2 wB = __ldg(wp + (size_t)(k+1)*64);   // k+1: {w_c0, w_c1}
        unsigned long long wA0, wA1, wB0, wB1;
        asm("mov.b64 %0,{%1,%1};" : "=l"(wA0) : "f"(wA.x));
        asm("mov.b64 %0,{%1,%1};" : "=l"(wA1) : "f"(wA.y));
        asm("mov.b64 %0,{%1,%1};" : "=l"(wB0) : "f"(wB.x));
        asm("mov.b64 %0,{%1,%1};" : "=l"(wB1) : "f"(wB.y));
        #pragma unroll
        for (int j = 0; j < 4; j++) {
            longlong2 q = *(const longlong2*)(base + j*640 + 2*k);   // LDS.128 broadcast
            asm("fma.rn.f32x2 %0,%1,%2,%0;" : "+l"(acc[j][0]) : "l"((unsigned long long)q.x), "l"(wA0));
            asm("fma.rn.f32x2 %0,%1,%2,%0;" : "+l"(acc[j][1]) : "l"((unsigned long long)q.x), "l"(wA1));
            asm("fma.rn.f32x2 %0,%1,%2,%0;" : "+l"(acc[j][0]) : "l"((unsigned long long)q.y), "l"(wB0));
            asm("fma.rn.f32x2 %0,%1,%2,%0;" : "+l"(acc[j][1]) : "l"((unsigned long long)q.y), "l"(wB1));
        }
    }

    float s0 = 0.f, q0 = 0.f, s1 = 0.f, q1 = 0.f;
    #pragma unroll
    for (int j = 0; j < 4; j++) {
        float e0, o0, e1, o1;
        asm("mov.b64 {%0,%1},%2;" : "=f"(e0), "=f"(o0) : "l"(acc[j][0]));
        asm("mov.b64 {%0,%1},%2;" : "=f"(e1), "=f"(o1) : "l"(acc[j][1]));
        int p = h*4 + j;
        *(float2*)(g_Z + (size_t)(r0 + 2*p    )*128 + c0) = make_float2(e0, e1);
        *(float2*)(g_Z + (size_t)(r0 + 2*p + 1)*128 + c0) = make_float2(o0, o1);
        s0 += e0 + o0;  q0 += e0*e0 + o0*o0;
        s1 += e1 + o1;  q1 += e1*e1 + o1*o1;
    }
    *(float2*)(g_psum + (size_t)(tile*2 + h)*128 + c0) = make_float2(s0, s1);
    *(float2*)(g_psq  + (size_t)(tile*2 + h)*128 + c0) = make_float2(q0, q1);
}

// Fused producer kernel with embedded tile GEMM ("last arriver executes").
// Tile t (16 rows) producers: bev blocks 4t..4t+3 (4 rows each) + sa blocks 2t, 2t+1 (8 kps each).
// Each producer: work -> __threadfence -> atomicAdd(tilecnt). The 6th finisher runs tile_gemm,
// so GEMM work hides under other blocks' DRAM-bound gathers. Values & fp order are identical
// regardless of which block executes -> deterministic.
__global__ void __launch_bounds__(256, 5) k_sabev(
    const float* __restrict__ kps, const float* __restrict__ pts,
    const float* __restrict__ pf,  const float* __restrict__ bev,
    const float* __restrict__ W1, const float* __restrict__ b1,
    const float* __restrict__ W2, const float* __restrict__ b2,
    const float* __restrict__ Wf)
{
    __shared__ union SH {
        float fsp[8*640];   // 20 KB GEMM workspace
        struct {
            float W1s[128], b1s[32], W2s[2048], b2s[64];
            int   cidx[8][128];
            float cd2 [8][128];
        } mlp;
    } sh;
    __shared__ int sh_win;

    int t = threadIdx.x;
    int m = blockIdx.x % 3;           // 0,1 -> bev ; 2 -> sa
    int g = blockIdx.x / 3;
    int tile;

    if (m < 2) {
        // ---- BEV gather: 4 rows per block; thread: 2 rows x 2 channels = 16 LDGs ----
        int bi   = 2*g + m;           // 0..2047
        tile     = bi >> 2;
        int c    = t & 127;
        int row0 = bi*4 + (t >> 7)*2;
        #pragma unroll
        for (int rr = 0; rr < 2; rr++) {
            int row = row0 + rr;
            int b = row >> 12;
            // match reference literally: (kx - 0)/0.16/1.0 ; (ky + 39.68)/0.16/1.0
            float x = kps[row*3+0] / 0.16f;
            float y = (kps[row*3+1] + 39.68f) / 0.16f;
            float fx = floorf(x), fy = floorf(y);
            int x0 = min(max((int)fx,     0), WW-1);
            int x1 = min(max((int)fx + 1, 0), WW-1);
            int y0 = min(max((int)fy,     0), HH-1);
            int y1 = min(max((int)fy + 1, 0), HH-1);
            float wa = ((float)x1 - x)*((float)y1 - y);
            float wb = ((float)x1 - x)*(y - (float)y0);
            float wc = (x - (float)x0)*((float)y1 - y);
            float wd = (x - (float)x0)*(y - (float)y0);
            const float* p0 = bev + ((size_t)b*CBEV + c)*(size_t)HW;
            const float* p1 = p0 + (size_t)128*HW;
            int oa = y0*WW + x0, ob = y1*WW + x0, oc = y0*WW + x1, od = y1*WW + x1;
            float A0 = __ldg(p0+oa), B0 = __ldg(p0+ob), C0 = __ldg(p0+oc), D0 = __ldg(p0+od);
            float A1 = __ldg(p1+oa), B1 = __ldg(p1+ob), C1 = __ldg(p1+oc), D1 = __ldg(p1+od);
            g_pbev[(size_t)row*CBEV + c]       = A0*wa + B0*wb + C0*wc + D0*wd;
            g_pbev[(size_t)row*CBEV + c + 128] = A1*wa + B1*wb + C1*wc + D1*wd;
        }
    } else {
        // ---- SA: one warp per keypoint, 8 warps per block ----
        tile = g >> 1;
        if (t < 128) sh.mlp.W1s[t] = W1[t];
        for (int i = t; i < 2048; i += 256) sh.mlp.W2s[i] = W2[i];
        if (t < 32) sh.mlp.b1s[t] = b1[t];
        if (t < 64) sh.mlp.b2s[t] = b2[t];
        __syncthreads();

        int warp = t >> 5, lane = t & 31;
        int kpi = g*8 + warp;             // 0..8191
        int b = kpi >> 12;
        float kx = kps[kpi*3+0], ky = kps[kpi*3+1], kz = kps[kpi*3+2];
        int cx = min(max(cellOf(kx,   0.0f), 0), GX-1);
        int cy = min(max(cellOf(ky, -39.68f),0), GY-1);
        int cz = min(max(cellOf(kz,  -3.0f), 0), GZ-1);

        const float* ptsb = pts + (size_t)b*NP*3;

        int n_l = 0;
        const int* cp_l = g_cellPts;
        if (lane < 27) {
            int ccx = cx + lane/9 - 1;
            int ccy = cy + (lane/3)%3 - 1;
            int ccz = cz + lane%3 - 1;
            if (ccx >= 0 && ccx < GX && ccy >= 0 && ccy < GY && ccz >= 0 && ccz < GZ) {
                int cell = b*NCELL + (ccx*GY + ccy)*GZ + ccz;
                n_l = min(g_cellCnt[cell], CAP);
                cp_l = &g_cellPts[cell*CAP];
            }
        }
        int maxn = n_l;
        #pragma unroll
        for (int o = 16; o; o >>= 1) maxn = max(maxn, __shfl_xor_sync(0xffffffffu, maxn, o));

        int cnt = 0;
        for (int s = 0; s < maxn; s++) {
            bool act = s < n_l;
            int pi = act ? cp_l[s] : 0;
            float d2 = 1e30f;
            if (act) {
                float ddx = ptsb[pi*3+0]-kx;
                float ddy = ptsb[pi*3+1]-ky;
                float ddz = ptsb[pi*3+2]-kz;
                d2 = ddx*ddx + ddy*ddy + ddz*ddz;
            }
            bool val = act && (d2 < R2);
            unsigned mm = __ballot_sync(0xffffffffu, val);
            int pos = cnt + __popc(mm & ((1u<<lane)-1u));
            if (val && pos < 128) { sh.mlp.cidx[warp][pos] = pi; sh.mlp.cd2[warp][pos] = d2; }
            cnt += __popc(mm);
        }
        if (cnt > 128) cnt = 128;
        __syncwarp();
        if (cnt > 32) {   // ultra-rare: keep 32 smallest d2 (same set as top_k; order irrelevant for maxpool)
            if (lane == 0) {
                for (int i = 32; i < cnt; i++) {
                    float d = sh.mlp.cd2[warp][i];
                    int mi = 0; float mv = sh.mlp.cd2[warp][0];
                    for (int j = 1; j < 32; j++) { float v = sh.mlp.cd2[warp][j]; if (v > mv) { mv = v; mi = j; } }
                    if (d < mv) { sh.mlp.cd2[warp][mi] = d; sh.mlp.cidx[warp][mi] = sh.mlp.cidx[warp][i]; }
                }
            }
            __syncwarp();
            cnt = 32;
        }

        float w10 = sh.mlp.W1s[lane], w11 = sh.mlp.W1s[32+lane];
        float w12 = sh.mlp.W1s[64+lane], w13 = sh.mlp.W1s[96+lane];
        float b1v = sh.mlp.b1s[lane];
        float a0 = 0.f, a1 = 0.f;   // relu >= 0 so 0-init == reference no-valid case
        const float* pfb = pf + (size_t)b*NP;
        for (int nIt = 0; nIt < cnt; nIt++) {
            int pi = sh.mlp.cidx[warp][nIt];
            float dx = ptsb[pi*3+0]-kx;
            float dy = ptsb[pi*3+1]-ky;
            float dz = ptsb[pi*3+2]-kz;
            float f  = pfb[pi];
            float hv = fmaxf(fmaf(dx,w10, fmaf(dy,w11, fmaf(dz,w12, fmaf(f,w13, b1v)))), 0.f);
            float t0 = sh.mlp.b2s[lane], t1 = sh.mlp.b2s[32+lane];
            #pragma unroll
            for (int j = 0; j < 32; j++) {
                float hj = __shfl_sync(0xffffffffu, hv, j);
                t0 = fmaf(hj, sh.mlp.W2s[j*64+lane],    t0);
                t1 = fmaf(hj, sh.mlp.W2s[j*64+32+lane], t1);
            }
            a0 = fmaxf(a0, fmaxf(t0, 0.f));
            a1 = fmaxf(a1, fmaxf(t1, 0.f));
        }
        g_sa[kpi*64 + lane]      = a0;
        g_sa[kpi*64 + 32 + lane] = a1;
    }

    // ---- release: make this block's writes visible, then count in ----
    __threadfence();
    __syncthreads();          // all threads' fences done; union no longer in mlp use
    if (t == 0) {
        int old = atomicAdd(&g_tilecnt[tile], 1);
        sh_win = (old == 5);
    }
    __syncthreads();
    if (sh_win) {
        __threadfence();      // acquire: flush L1 before reading other blocks' g_sa/g_pbev
        tile_gemm(tile, Wf, sh.fsp);
    }
}

// One block per channel; 256 threads reduce 1024 partials. Deterministic.
__global__ void __launch_bounds__(256) k_stats(
    const float* __restrict__ gamma, const float* __restrict__ beta)
{
    __shared__ float sh_s[256], sh_q[256];
    int c = blockIdx.x, t = threadIdx.x;
    float s = 0.f, q = 0.f;
    #pragma unroll
    for (int i = t; i < NPART; i += 256) { s += g_psum[i*128+c]; q += g_psq[i*128+c]; }
    sh_s[t] = s; sh_q[t] = q;
    __syncthreads();
    #pragma unroll
    for (int o = 128; o; o >>= 1) {
        if (t < o) { sh_s[t] += sh_s[t+o]; sh_q[t] += sh_q[t+o]; }
        __syncthreads();
    }
    if (t == 0) {
        float inv = 1.0f / (float)NKP;
        float mu  = sh_s[0] * inv;
        float var = sh_q[0] * inv - mu*mu;
        float sc  = rsqrtf(var + 1e-5f) * gamma[c];
        g_scale[c] = sc;
        g_shift[c] = beta[c] - mu * sc;
    }
}

__global__ void k_norm(float* __restrict__ out) {
    int i = blockIdx.x*blockDim.x + threadIdx.x;
    int c = i & 127;
    out[i] = fmaxf(fmaf(g_Z[i], g_scale[c], g_shift[c]), 0.f);
}

extern "C" void kernel_launch(void* const* d_in, const int* /*in_sizes*/, int /*n_in*/,
                              void* d_out, int /*out_size*/) {
    const float* kps = (const float*)d_in[0];
    const float* pts = (const float*)d_in[1];
    const float* pf  = (const float*)d_in[2];
    const float* bev = (const float*)d_in[3];
    const float* W1  = (const float*)d_in[4];
    const float* b1  = (const float*)d_in[5];
    const float* W2  = (const float*)d_in[6];
    const float* b2  = (const float*)d_in[7];
    const float* Wf  = (const float*)d_in[8];
    const float* gm  = (const float*)d_in[9];
    const float* bt  = (const float*)d_in[10];

    // zero counters via async memset (graph-capturable, no allocation)
    void* pCell = nullptr; void* pTile = nullptr;
    cudaGetSymbolAddress(&pCell, g_cellCnt);
    cudaGetSymbolAddress(&pTile, g_tilecnt);
    cudaMemsetAsync(pCell, 0, sizeof(int)*NB*NCELL);
    cudaMemsetAsync(pTile, 0, sizeof(int)*NTILES);

    k_bin  <<<(NB*NP + 255)/256, 256>>>(pts);
    k_sabev<<<BEV_BLKS + SA_BLKS, 256>>>(kps, pts, pf, bev, W1, b1, W2, b2, Wf);
    k_stats<<<128, 256>>>(gm, bt);
    k_norm <<<(NKP*128)/256, 256>>>((float*)d_out);
}

// round 11
// speedup vs baseline: 1.1444x; 1.0154x over previous
#include <cuda_runtime.h>
#include <math.h>

// Problem constants
#define NB   2
#define NK   4096
#define NP   16384
#define NKP  (NB*NK)          // 8192 keypoint rows
#define CBEV 256
#define HH   496
#define WW   432
#define HW   (HH*WW)
#define R2   0.64f

// Grid for ball query (cell size = radius = 0.8)
#define GX 87
#define GY 100
#define GZ 5
#define NCELL (GX*GY*GZ)      // 43500
#define CAP 32

#define NTILES (NKP/16)       // 512 tiles of 16 rows
#define NPART (NTILES*2)      // 1024 BN partial sets
#define BEV_BLKS (NKP/4)      // 2048 bev blocks, 4 rows each
#define SA_BLKS  (NKP/8)      // 1024 sa blocks, 8 keypoints each

// ---- scratch (static device globals; no allocation) ----
__device__ int   g_cellCnt[NB*NCELL];
__device__ int   g_cellPts[NB*NCELL*CAP];
__device__ int   g_tilecnt[NTILES];
__device__ float g_sa[NKP*64];
__device__ float g_pbev[NKP*CBEV];
__device__ float g_Z[NKP*128];
__device__ float g_psum[NPART*128];
__device__ float g_psq [NPART*128];
__device__ float g_scale[128];
__device__ float g_shift[128];

__device__ __forceinline__ int cellOf(float x, float lo) {
    return (int)floorf((x - lo) * 1.25f);
}

__global__ void k_init() {
    int i = blockIdx.x*blockDim.x + threadIdx.x;
    if (i < NB*NCELL) g_cellCnt[i] = 0;
    if (i < NTILES)   g_tilecnt[i] = 0;
}

__global__ void k_bin(const float* __restrict__ pts) {
    int i = blockIdx.x*blockDim.x + threadIdx.x;
    if (i >= NB*NP) return;
    int b = i / NP, p = i % NP;
    float x = pts[i*3+0], y = pts[i*3+1], z = pts[i*3+2];
    int cx = min(max(cellOf(x,   0.0f), 0), GX-1);
    int cy = min(max(cellOf(y, -39.68f),0), GY-1);
    int cz = min(max(cellOf(z,  -3.0f), 0), GZ-1);
    int cell = b*NCELL + (cx*GY + cy)*GZ + cz;
    int slot = atomicAdd(&g_cellCnt[cell], 1);
    if (slot < CAP) g_cellPts[cell*CAP + slot] = p;   // set semantics; order-invariant downstream
}

// Warm L2 with Wf (160 KB) so tile_gemm weight reads never cold-miss.
__global__ void k_pre(const float* __restrict__ Wf) {
    int i = blockIdx.x*blockDim.x + threadIdx.x;      // 10240 threads x 16B
    if (i < (320*128)/4)
        asm volatile("prefetch.global.L2 [%0];" :: "l"(Wf + (size_t)i*4));
}

// Full-K tile GEMM + BN partials. Stage with 256 threads; compute with 128 threads:
// thread (h = t>>6 in 0..1, cp = t&63) owns 8 rows (pairs h*4..h*4+3) x 2 cols {2cp,2cp+1}.
// Per k-pair iter: 2 LDG.64 + 4 packs + 4 LDS.128 + 16 FFMA2  (0.81 instr/MAC, low L1/MAC).
// fma.rn.f32x2 is bit-identical to 2x scalar fma.rn.
__device__ __forceinline__ void tile_gemm(int tile, const float* __restrict__ Wf, float* fsp) {
    int t = threadIdx.x;
    int r0 = tile * 16;
    for (int i = t; i < 16*320; i += 256) {
        int r = i / 320, k = i - r*320;
        float v = (k < 64) ? g_sa[(size_t)(r0+r)*64 + k]
                           : g_pbev[(size_t)(r0+r)*CBEV + (k-64)];
        fsp[(r>>1)*640 + 2*k + (r&1)] = v;
    }
    __syncthreads();
    if (t >= 128) return;

    int h = t >> 6, cp = t & 63;
    int c0 = 2*cp;
    unsigned long long acc[4][2];
    #pragma unroll
    for (int j = 0; j < 4; j++) { acc[j][0] = 0ull; acc[j][1] = 0ull; }

    const float2* wp = (const float2*)Wf + cp;     // element (k, colpair cp) at k*64+cp
    const float* base = fsp + (h*4)*640;
    for (int k = 0; k < 320; k += 2) {
        float2 wA = __ldg(wp + (size_t)k*64);       // k:   {w_c0, w_c1}
        float2 wB = __ldg(wp + (size_t)(k+1)*64);   // k+1: {w_c0, w_c1}
        unsigned long long wA0, wA1, wB0, wB1;
        asm("mov.b64 %0,{%1,%1};" : "=l"(wA0) : "f"(wA.x));
        asm("mov.b64 %0,{%1,%1};" : "=l"(wA1) : "f"(wA.y));
        asm("mov.b64 %0,{%1,%1};" : "=l"(wB0) : "f"(wB.x));
        asm("mov.b64 %0,{%1,%1};" : "=l"(wB1) : "f"(wB.y));
        #pragma unroll
        for (int j = 0; j < 4; j++) {
            longlong2 q = *(const longlong2*)(base + j*640 + 2*k);   // LDS.128 broadcast
            asm("fma.rn.f32x2 %0,%1,%2,%0;" : "+l"(acc[j][0]) : "l"((unsigned long long)q.x), "l"(wA0));
            asm("fma.rn.f32x2 %0,%1,%2,%0;" : "+l"(acc[j][1]) : "l"((unsigned long long)q.x), "l"(wA1));
            asm("fma.rn.f32x2 %0,%1,%2,%0;" : "+l"(acc[j][0]) : "l"((unsigned long long)q.y), "l"(wB0));
            asm("fma.rn.f32x2 %0,%1,%2,%0;" : "+l"(acc[j][1]) : "l"((unsigned long long)q.y), "l"(wB1));
        }
    }

    float s0 = 0.f, q0 = 0.f, s1 = 0.f, q1 = 0.f;
    #pragma unroll
    for (int j = 0; j < 4; j++) {
        float e0, o0, e1, o1;
        asm("mov.b64 {%0,%1},%2;" : "=f"(e0), "=f"(o0) : "l"(acc[j][0]));
        asm("mov.b64 {%0,%1},%2;" : "=f"(e1), "=f"(o1) : "l"(acc[j][1]));
        int p = h*4 + j;
        *(float2*)(g_Z + (size_t)(r0 + 2*p    )*128 + c0) = make_float2(e0, e1);
        *(float2*)(g_Z + (size_t)(r0 + 2*p + 1)*128 + c0) = make_float2(o0, o1);
        s0 += e0 + o0;  q0 += e0*e0 + o0*o0;
        s1 += e1 + o1;  q1 += e1*e1 + o1*o1;
    }
    *(float2*)(g_psum + (size_t)(tile*2 + h)*128 + c0) = make_float2(s0, s1);
    *(float2*)(g_psq  + (size_t)(tile*2 + h)*128 + c0) = make_float2(q0, q1);
}

// Fused producer kernel with embedded tile GEMM ("last arriver executes").
// Tile t (16 rows) producers: bev blocks 4t..4t+3 (4 rows each) + sa blocks 2t, 2t+1 (8 kps each).
// Each producer: work -> __threadfence -> atomicAdd(tilecnt). The 6th finisher runs tile_gemm,
// so GEMM work hides under other blocks' DRAM-bound gathers. Values & fp order are identical
// regardless of which block executes -> deterministic.
__global__ void __launch_bounds__(256, 5) k_sabev(
    const float* __restrict__ kps, const float* __restrict__ pts,
    const float* __restrict__ pf,  const float* __restrict__ bev,
    const float* __restrict__ W1, const float* __restrict__ b1,
    const float* __restrict__ W2, const float* __restrict__ b2,
    const float* __restrict__ Wf)
{
    __shared__ union SH {
        float fsp[8*640];   // 20 KB GEMM workspace
        struct {
            float W1s[128], b1s[32], W2s[2048], b2s[64];
            int   cidx[8][128];
            float cd2 [8][128];
        } mlp;
    } sh;
    __shared__ int sh_win;

    int t = threadIdx.x;
    int m = blockIdx.x % 3;           // 0,1 -> bev ; 2 -> sa
    int g = blockIdx.x / 3;
    int tile;

    if (m < 2) {
        // ---- BEV gather: 4 rows per block; thread: 2 rows x 2 channels = 16 LDGs ----
        int bi   = 2*g + m;           // 0..2047
        tile     = bi >> 2;
        int c    = t & 127;
        int row0 = bi*4 + (t >> 7)*2;
        #pragma unroll
        for (int rr = 0; rr < 2; rr++) {
            int row = row0 + rr;
            int b = row >> 12;
            // match reference literally: (kx - 0)/0.16/1.0 ; (ky + 39.68)/0.16/1.0
            float x = kps[row*3+0] / 0.16f;
            float y = (kps[row*3+1] + 39.68f) / 0.16f;
            float fx = floorf(x), fy = floorf(y);
            int x0 = min(max((int)fx,     0), WW-1);
            int x1 = min(max((int)fx + 1, 0), WW-1);
            int y0 = min(max((int)fy,     0), HH-1);
            int y1 = min(max((int)fy + 1, 0), HH-1);
            float wa = ((float)x1 - x)*((float)y1 - y);
            float wb = ((float)x1 - x)*(y - (float)y0);
            float wc = (x - (float)x0)*((float)y1 - y);
            float wd = (x - (float)x0)*(y - (float)y0);
            const float* p0 = bev + ((size_t)b*CBEV + c)*(size_t)HW;
            const float* p1 = p0 + (size_t)128*HW;
            int oa = y0*WW + x0, ob = y1*WW + x0, oc = y0*WW + x1, od = y1*WW + x1;
            float A0 = __ldg(p0+oa), B0 = __ldg(p0+ob), C0 = __ldg(p0+oc), D0 = __ldg(p0+od);
            float A1 = __ldg(p1+oa), B1 = __ldg(p1+ob), C1 = __ldg(p1+oc), D1 = __ldg(p1+od);
            g_pbev[(size_t)row*CBEV + c]       = A0*wa + B0*wb + C0*wc + D0*wd;
            g_pbev[(size_t)row*CBEV + c + 128] = A1*wa + B1*wb + C1*wc + D1*wd;
        }
    } else {
        // ---- SA: one warp per keypoint, 8 warps per block ----
        tile = g >> 1;
        if (t < 128) sh.mlp.W1s[t] = W1[t];
        for (int i = t; i < 2048; i += 256) sh.mlp.W2s[i] = W2[i];
        if (t < 32) sh.mlp.b1s[t] = b1[t];
        if (t < 64) sh.mlp.b2s[t] = b2[t];
        __syncthreads();

        int warp = t >> 5, lane = t & 31;
        int kpi = g*8 + warp;             // 0..8191
        int b = kpi >> 12;
        float kx = kps[kpi*3+0], ky = kps[kpi*3+1], kz = kps[kpi*3+2];
        int cx = min(max(cellOf(kx,   0.0f), 0), GX-1);
        int cy = min(max(cellOf(ky, -39.68f),0), GY-1);
        int cz = min(max(cellOf(kz,  -3.0f), 0), GZ-1);

        const float* ptsb = pts + (size_t)b*NP*3;

        int n_l = 0;
        const int* cp_l = g_cellPts;
        if (lane < 27) {
            int ccx = cx + lane/9 - 1;
            int ccy = cy + (lane/3)%3 - 1;
            int ccz = cz + lane%3 - 1;
            if (ccx >= 0 && ccx < GX && ccy >= 0 && ccy < GY && ccz >= 0 && ccz < GZ) {
                int cell = b*NCELL + (ccx*GY + ccy)*GZ + ccz;
                n_l = min(g_cellCnt[cell], CAP);
                cp_l = &g_cellPts[cell*CAP];
            }
        }
        int maxn = n_l;
        #pragma unroll
        for (int o = 16; o; o >>= 1) maxn = max(maxn, __shfl_xor_sync(0xffffffffu, maxn, o));

        int cnt = 0;
        for (int s = 0; s < maxn; s++) {
            bool act = s < n_l;
            int pi = act ? cp_l[s] : 0;
            float d2 = 1e30f;
            if (act) {
                float ddx = ptsb[pi*3+0]-kx;
                float ddy = ptsb[pi*3+1]-ky;
                float ddz = ptsb[pi*3+2]-kz;
                d2 = ddx*ddx + ddy*ddy + ddz*ddz;
            }
            bool val = act && (d2 < R2);
            unsigned mm = __ballot_sync(0xffffffffu, val);
            int pos = cnt + __popc(mm & ((1u<<lane)-1u));
            if (val && pos < 128) { sh.mlp.cidx[warp][pos] = pi; sh.mlp.cd2[warp][pos] = d2; }
            cnt += __popc(mm);
        }
        if (cnt > 128) cnt = 128;
        __syncwarp();
        if (cnt > 32) {   // ultra-rare: keep 32 smallest d2 (same set as top_k; order irrelevant for maxpool)
            if (lane == 0) {
                for (int i = 32; i < cnt; i++) {
                    float d = sh.mlp.cd2[warp][i];
                    int mi = 0; float mv = sh.mlp.cd2[warp][0];
                    for (int j = 1; j < 32; j++) { float v = sh.mlp.cd2[warp][j]; if (v > mv) { mv = v; mi = j; } }
                    if (d < mv) { sh.mlp.cd2[warp][mi] = d; sh.mlp.cidx[warp][mi] = sh.mlp.cidx[warp][i]; }
                }
            }
            __syncwarp();
            cnt = 32;
        }

        float w10 = sh.mlp.W1s[lane], w11 = sh.mlp.W1s[32+lane];
        float w12 = sh.mlp.W1s[64+lane], w13 = sh.mlp.W1s[96+lane];
        float b1v = sh.mlp.b1s[lane];
        float a0 = 0.f, a1 = 0.f;   // relu >= 0 so 0-init == reference no-valid case
        const float* pfb = pf + (size_t)b*NP;
        for (int nIt = 0; nIt < cnt; nIt++) {
            int pi = sh.mlp.cidx[warp][nIt];
            float dx = ptsb[pi*3+0]-kx;
            float dy = ptsb[pi*3+1]-ky;
            float dz = ptsb[pi*3+2]-kz;
            float f  = pfb[pi];
            float hv = fmaxf(fmaf(dx,w10, fmaf(dy,w11, fmaf(dz,w12, fmaf(f,w13, b1v)))), 0.f);
            float t0 = sh.mlp.b2s[lane], t1 = sh.mlp.b2s[32+lane];
            #pragma unroll
            for (int j = 0; j < 32; j++) {
                float hj = __shfl_sync(0xffffffffu, hv, j);
                t0 = fmaf(hj, sh.mlp.W2s[j*64+lane],    t0);
                t1 = fmaf(hj, sh.mlp.W2s[j*64+32+lane], t1);
            }
            a0 = fmaxf(a0, fmaxf(t0, 0.f));
            a1 = fmaxf(a1, fmaxf(t1, 0.f));
        }
        g_sa[kpi*64 + lane]      = a0;
        g_sa[kpi*64 + 32 + lane] = a1;
    }

    // ---- release: make this block's writes visible, then count in ----
    __threadfence();
    __syncthreads();          // all threads' fences done; union no longer in mlp use
    if (t == 0) {
        int old = atomicAdd(&g_tilecnt[tile], 1);
        sh_win = (old == 5);
    }
    __syncthreads();
    if (sh_win) {
        __threadfence();      // acquire: flush L1 before reading other blocks' g_sa/g_pbev
        tile_gemm(tile, Wf, sh.fsp);
    }
}

// One block per channel; 256 threads reduce 1024 partials. Deterministic.
__global__ void __launch_bounds__(256) k_stats(
    const float* __restrict__ gamma, const float* __restrict__ beta)
{
    __shared__ float sh_s[256], sh_q[256];
    int c = blockIdx.x, t = threadIdx.x;
    float s = 0.f, q = 0.f;
    #pragma unroll
    for (int i = t; i < NPART; i += 256) { s += g_psum[i*128+c]; q += g_psq[i*128+c]; }
    sh_s[t] = s; sh_q[t] = q;
    __syncthreads();
    #pragma unroll
    for (int o = 128; o; o >>= 1) {
        if (t < o) { sh_s[t] += sh_s[t+o]; sh_q[t] += sh_q[t+o]; }
        __syncthreads();
    }
    if (t == 0) {
        float inv = 1.0f / (float)NKP;
        float mu  = sh_s[0] * inv;
        float var = sh_q[0] * inv - mu*mu;
        float sc  = rsqrtf(var + 1e-5f) * gamma[c];
        g_scale[c] = sc;
        g_shift[c] = beta[c] - mu * sc;
    }
}

// Vectorized normalize: one float4 per thread (1 LDG.128 + 1 STG.128).
__global__ void k_norm(float4* __restrict__ out) {
    int i = blockIdx.x*blockDim.x + threadIdx.x;      // 0 .. NKP*32-1
    int c4 = i & 31;
    float4 z  = ((const float4*)g_Z)[i];
    float4 sc = ((const float4*)g_scale)[c4];
    float4 sf = ((const float4*)g_shift)[c4];
    float4 r;
    r.x = fmaxf(fmaf(z.x, sc.x, sf.x), 0.f);
    r.y = fmaxf(fmaf(z.y, sc.y, sf.y), 0.f);
    r.z = fmaxf(fmaf(z.z, sc.z, sf.z), 0.f);
    r.w = fmaxf(fmaf(z.w, sc.w, sf.w), 0.f);
    out[i] = r;
}

extern "C" void kernel_launch(void* const* d_in, const int* /*in_sizes*/, int /*n_in*/,
                              void* d_out, int /*out_size*/) {
    const float* kps = (const float*)d_in[0];
    const float* pts = (const float*)d_in[1];
    const float* pf  = (const float*)d_in[2];
    const float* bev = (const float*)d_in[3];
    const float* W1  = (const float*)d_in[4];
    const float* b1  = (const float*)d_in[5];
    const float* W2  = (const float*)d_in[6];
    const float* b2  = (const float*)d_in[7];
    const float* Wf  = (const float*)d_in[8];
    const float* gm  = (const float*)d_in[9];
    const float* bt  = (const float*)d_in[10];

    k_init <<<(NB*NCELL + 255)/256, 256>>>();                 // kernel 1
    k_bin  <<<(NB*NP    + 255)/256, 256>>>(pts);              // kernel 2
    k_pre  <<<40, 256>>>(Wf);                                 // kernel 3 (L2 warm)
    k_sabev<<<BEV_BLKS + SA_BLKS, 256>>>(kps, pts, pf, bev,   // kernel 4 -> profiled
                                         W1, b1, W2, b2, Wf);
    k_stats<<<128, 256>>>(gm, bt);                            // kernel 5
    k_norm <<<(NKP*32)/256, 256>>>((float4*)d_out);           // kernel 6
}